// round 12
// baseline (speedup 1.0000x reference)
#include <cuda_runtime.h>
#include <cuda_bf16.h>

// Problem constants: T=1024, C_in=4, C_out=2, H=32
#define T_LEN 1024
#define H_DIM 32
#define NPAIR 128          // (h,c) pairs
#define GRID  129          // 128 pair CTAs + 1 channel-summed plain-x CTA
#define INV_T (1.0f / 1024.0f)

// Interleaved scan storage: g_SC4[p][k] = (S[2k], C[2k], S[2k+1], C[2k+1]).
// Phase-1: coalesced STG.128. Phase-2: each thread's 2 LDG.128 share a sector.
__device__ float4 g_SC4[NPAIR][T_LEN / 2];
__device__ float  g_X[T_LEN];             // prefix of sum_c x (b2 term)
__device__ unsigned int g_ctr;            // monotonic generation barrier

// ---------------------------------------------------------------------------
// Fused CKConv via prefix-scan factorization (O(T*H*C)):
//   pair (h,c) contributes  A*(ci*S - si*C) + B*(si*S + ci*C) to y[i,o],
//   A = w2*cos(phi), B = w2*sin(phi), phi = c*w1[h,1] + o*w1[h,2] + b1[h],
//   (si,ci) = sincos(w1[h,0] t_i), S/C = prefixes of sin/cos(w1[h,0] t_j) x[j,c].
// Phase 1: CTA p scans pair p (CTA 128: channel-summed plain scan -> g_X).
// Barrier: 1 atomic/CTA + all-thread spin on smem-broadcast target (warps
// wake independently; no post-spin __syncthreads).
// Phase 2 (CTAs 0..31 only, 32 rows each): warp = 4 rows, lane = h, c serial;
// fully warp-local (loads + FMA + butterfly + store), zero smem/sync.
// ---------------------------------------------------------------------------
__global__ void __launch_bounds__(256)
ck_fused_kernel(const float* __restrict__ x,   // [T,4]
                const float* __restrict__ w1,  // [H,3]
                const float* __restrict__ b1,  // [H]
                const float* __restrict__ w2,  // [H]
                const float* __restrict__ b2,  // [1]
                float* __restrict__ y)         // [T,2]
{
    const int tid  = threadIdx.x;
    const int warp = tid >> 5;
    const int lane = tid & 31;
    const int p    = blockIdx.x;

    __shared__ float4 sAB[NPAIR];       // (A0,B0,A1,B1) per pair
    __shared__ float  wtS[8], wtC[8];   // phase-1 warp totals
    __shared__ unsigned int s_target;   // barrier target broadcast

    // ---- Constant table (256 threads = 128 pairs x 2 outputs) ----------
    {
        int pr = tid >> 1, o = tid & 1;
        int h = pr >> 2, c = pr & 3;
        float ph = fmaf((float)c, __ldg(&w1[3 * h + 1]),
                    fmaf((float)o, __ldg(&w1[3 * h + 2]), __ldg(&b1[h])));
        float s, cc;
        __sincosf(ph, &s, &cc);
        float w = __ldg(&w2[h]);
        float* dst = (float*)&sAB[pr];
        dst[2 * o]     = w * cc;
        dst[2 * o + 1] = w * s;
    }

    // ---- Pre-barrier phase-2 prep (inputs only; overlaps phase 1) ------
    // CTA b < 32 covers rows [32b, 32b+32); warp = rows i0..i0+3; lane = h.
    const int i0 = blockIdx.x * 32 + warp * 4;
    float p2si[4], p2ci[4];
    float ah = __ldg(&w1[3 * lane]);
#pragma unroll
    for (int r = 0; r < 4; ++r)
        __sincosf(ah * (float)(i0 + r) * INV_T, &p2si[r], &p2ci[r]);
    const float b2v = __ldg(&b2[0]);

    // ---- Phase 1: scan task p over j = 4*tid .. 4*tid+3 ----------------
    {
        const float a = (p < NPAIR) ? __ldg(&w1[3 * (p >> 2)]) : 0.0f;
        const int   c = p & 3;
        const int   j0 = tid * 4;

        float S[4], C[4], sS = 0.0f, sC = 0.0f;
#pragma unroll
        for (int k = 0; k < 4; ++k) {
            int j = j0 + k;
            float4 xr = __ldg(&((const float4*)x)[j]);
            float xv;
            if (p < NPAIR) {
                xv = (c == 0) ? xr.x : (c == 1) ? xr.y : (c == 2) ? xr.z : xr.w;
            } else {
                xv = (xr.x + xr.y) + (xr.z + xr.w);   // channel-summed
            }
            float sj, cj;
            __sincosf(a * (float)j * INV_T, &sj, &cj); // t_j = j/1024 exact
            sS = fmaf(sj, xv, sS);  S[k] = sS;
            sC = fmaf(cj, xv, sC);  C[k] = sC;
        }

        float iS = sS, iC = sC;
#pragma unroll
        for (int o2 = 1; o2 < 32; o2 <<= 1) {
            float nS = __shfl_up_sync(0xffffffffu, iS, o2);
            float nC = __shfl_up_sync(0xffffffffu, iC, o2);
            if (lane >= o2) { iS += nS; iC += nC; }
        }
        if (lane == 31) { wtS[warp] = iS; wtC[warp] = iC; }
        float eS = iS - sS, eC = iC - sC;
        __syncthreads();

        float bS = eS, bC = eC;
#pragma unroll
        for (int w = 0; w < 8; ++w) {
            if (w < warp) { bS += wtS[w]; bC += wtC[w]; }
        }

        if (p < NPAIR) {
            g_SC4[p][2 * tid]     = make_float4(S[0] + bS, C[0] + bC,
                                                S[1] + bS, C[1] + bC);
            g_SC4[p][2 * tid + 1] = make_float4(S[2] + bS, C[2] + bC,
                                                S[3] + bS, C[3] + bC);
        } else {
            ((float4*)g_X)[tid] = make_float4(C[0] + bC, C[1] + bC,
                                              C[2] + bC, C[3] + bC);
        }
    }
    __syncthreads();

    // ---- Barrier: tid0 fence+arrive+broadcast; all threads spin --------
    if (tid == 0) {
        __threadfence();                       // cumulative release
        unsigned int ticket = atomicAdd(&g_ctr, 1u);
        s_target = (ticket / GRID + 1u) * GRID;
    }
    __syncthreads();
    if (blockIdx.x >= 32) return;              // scan-only CTAs are done

    const unsigned int target = s_target;
    while (*(volatile unsigned int*)&g_ctr < target) { }
    __threadfence();                           // cumulative acquire

    // ---- Phase 2: warp-local. lane = h; pairs 4*lane..4*lane+3 ---------
    {
        const int k0 = i0 >> 1;                // even: both loads same sector
        float y0[4] = {0.f, 0.f, 0.f, 0.f};
        float y1[4] = {0.f, 0.f, 0.f, 0.f};

#pragma unroll
        for (int c = 0; c < 4; ++c) {
            const int pr = 4 * lane + c;
            float4 v0 = g_SC4[pr][k0];         // rows i0, i0+1  (S,C,S,C)
            float4 v1 = g_SC4[pr][k0 + 1];     // rows i0+2, i0+3
            float4 ab = sAB[pr];
            const float Sv[4] = {v0.x, v0.z, v1.x, v1.z};
            const float Cv[4] = {v0.y, v0.w, v1.y, v1.w};
#pragma unroll
            for (int r = 0; r < 4; ++r) {
                float u = fmaf(p2ci[r], Sv[r], -p2si[r] * Cv[r]);
                float v = fmaf(p2si[r], Sv[r],  p2ci[r] * Cv[r]);
                y0[r] = fmaf(ab.x, u, fmaf(ab.y, v, y0[r]));
                y1[r] = fmaf(ab.z, u, fmaf(ab.w, v, y1[r]));
            }
        }
        if (lane == 0) {                       // b2 * prefix(sum_c x)
#pragma unroll
            for (int r = 0; r < 4; ++r) {
                float e = b2v * g_X[i0 + r];
                y0[r] += e; y1[r] += e;
            }
        }

        // Butterfly over lanes (h); 8 chains pipeline the shuffle latency.
#pragma unroll
        for (int off = 16; off > 0; off >>= 1) {
#pragma unroll
            for (int r = 0; r < 4; ++r) {
                y0[r] += __shfl_xor_sync(0xffffffffu, y0[r], off);
                y1[r] += __shfl_xor_sync(0xffffffffu, y1[r], off);
            }
        }
        if (lane == 0) {
#pragma unroll
            for (int r = 0; r < 4; ++r)
                ((float2*)y)[i0 + r] = make_float2(y0[r], y1[r]);
        }
    }
}

// ---------------------------------------------------------------------------
// Inputs (metadata order): x[T*4], t[T], w1[H*3], b1[H], w2[H], b2[1],
// out_channels (unused; t = arange/T is exact fp32, computed inline).
// ---------------------------------------------------------------------------
extern "C" void kernel_launch(void* const* d_in, const int* in_sizes, int n_in,
                              void* d_out, int out_size)
{
    const float* x  = (const float*)d_in[0];
    const float* w1 = (const float*)d_in[2];
    const float* b1 = (const float*)d_in[3];
    const float* w2 = (const float*)d_in[4];
    const float* b2 = (const float*)d_in[5];
    float* y = (float*)d_out;

    ck_fused_kernel<<<GRID, 256>>>(x, w1, b1, w2, b2, y);
}

// round 13
// speedup vs baseline: 1.0276x; 1.0276x over previous
#include <cuda_runtime.h>
#include <cuda_bf16.h>

// Problem constants: T=1024, C_in=4, C_out=2, H=32
#define T_LEN 1024
#define H_DIM 32
#define NPAIR 128          // (h,c) pairs
#define INV_T (1.0f / 1024.0f)

// Interleaved scan storage: g_SC4[p][k] = (S[2k], C[2k], S[2k+1], C[2k+1]).
// Scan writes: coalesced STG.128. Combine: each thread's 2 LDG.128 share a
// 32B sector. 1 MB total, L2-resident.
__device__ float4 g_SC4[NPAIR][T_LEN / 2];
__device__ float  g_X[T_LEN];             // prefix of sum_c x (b2 term)

// ---------------------------------------------------------------------------
// CKConv via prefix-scan factorization (O(T*H*C)):
//   pair (h,c) contributes  A*(ci*S - si*C) + B*(si*S + ci*C) to y[i,o],
//   A = w2*cos(phi), B = w2*sin(phi), phi = c*w1[h,1] + o*w1[h,2] + b1[h],
//   (si,ci) = sincos(w1[h,0] t_i),
//   S/C[i] = prefix sums of sin/cos(w1[h,0] t_j) * x[j,c].
// Kernel A: CTA p scans pair p (CTA 128: channel-summed plain scan -> g_X).
// Kernel B: combine; ordering via the graph edge (no barrier, no atomics).
// ---------------------------------------------------------------------------

__global__ void __launch_bounds__(256)
ck_scan_kernel(const float* __restrict__ x,   // [T,4]
               const float* __restrict__ w1)  // [H,3]
{
    const int tid  = threadIdx.x;
    const int warp = tid >> 5;
    const int lane = tid & 31;
    const int p    = blockIdx.x;

    __shared__ float wtS[8], wtC[8];    // per-warp scan totals

    const float a = (p < NPAIR) ? __ldg(&w1[3 * (p >> 2)]) : 0.0f;
    const int   c = p & 3;
    const int   j0 = tid * 4;

    float S[4], C[4], sS = 0.0f, sC = 0.0f;
#pragma unroll
    for (int k = 0; k < 4; ++k) {
        int j = j0 + k;
        float4 xr = __ldg(&((const float4*)x)[j]);
        float xv;
        if (p < NPAIR) {
            xv = (c == 0) ? xr.x : (c == 1) ? xr.y : (c == 2) ? xr.z : xr.w;
        } else {
            xv = (xr.x + xr.y) + (xr.z + xr.w);   // channel-summed
        }
        float sj, cj;
        __sincosf(a * (float)j * INV_T, &sj, &cj);  // t_j = j/1024 exact
        sS = fmaf(sj, xv, sS);  S[k] = sS;
        sC = fmaf(cj, xv, sC);  C[k] = sC;
    }

    // Warp inclusive scan of thread totals -> exclusive thread offsets.
    float iS = sS, iC = sC;
#pragma unroll
    for (int o2 = 1; o2 < 32; o2 <<= 1) {
        float nS = __shfl_up_sync(0xffffffffu, iS, o2);
        float nC = __shfl_up_sync(0xffffffffu, iC, o2);
        if (lane >= o2) { iS += nS; iC += nC; }
    }
    if (lane == 31) { wtS[warp] = iS; wtC[warp] = iC; }
    float eS = iS - sS, eC = iC - sC;
    __syncthreads();

    float bS = eS, bC = eC;
#pragma unroll
    for (int w = 0; w < 8; ++w) {
        if (w < warp) { bS += wtS[w]; bC += wtC[w]; }
    }

    if (p < NPAIR) {       // interleaved, coalesced (2 x STG.128)
        g_SC4[p][2 * tid]     = make_float4(S[0] + bS, C[0] + bC,
                                            S[1] + bS, C[1] + bC);
        g_SC4[p][2 * tid + 1] = make_float4(S[2] + bS, C[2] + bC,
                                            S[3] + bS, C[3] + bC);
    } else {               // plain channel-summed prefix (a=0 -> C path)
        ((float4*)g_X)[tid] = make_float4(C[0] + bC, C[1] + bC,
                                          C[2] + bC, C[3] + bC);
    }
}

// Combine: 32 CTAs x 256. Warp = rows i0..i0+3, lane = h (pairs 4h..4h+3).
// Fully warp-local after the const table: loads + FMA + butterfly + store.
__global__ void __launch_bounds__(256)
ck_combine_kernel(const float* __restrict__ w1,  // [H,3]
                  const float* __restrict__ b1,  // [H]
                  const float* __restrict__ w2,  // [H]
                  const float* __restrict__ b2,  // [1]
                  float* __restrict__ y)         // [T,2]
{
    const int tid  = threadIdx.x;
    const int warp = tid >> 5;
    const int lane = tid & 31;

    __shared__ float4 sAB[NPAIR];       // (A0,B0,A1,B1) per pair

    // Const table: 256 threads = 128 pairs x 2 outputs, one sincos each.
    {
        int pr = tid >> 1, o = tid & 1;
        int h = pr >> 2, c = pr & 3;
        float ph = fmaf((float)c, __ldg(&w1[3 * h + 1]),
                    fmaf((float)o, __ldg(&w1[3 * h + 2]), __ldg(&b1[h])));
        float s, cc;
        __sincosf(ph, &s, &cc);
        float w = __ldg(&w2[h]);
        float* dst = (float*)&sAB[pr];
        dst[2 * o]     = w * cc;
        dst[2 * o + 1] = w * s;
    }

    const int i0 = blockIdx.x * 32 + warp * 4;   // this warp's 4 rows
    const int k0 = i0 >> 1;                      // even: sector-shared loads

    // Row rotation angles (lane = h).
    float p2si[4], p2ci[4];
    const float ah = __ldg(&w1[3 * lane]);
#pragma unroll
    for (int r = 0; r < 4; ++r)
        __sincosf(ah * (float)(i0 + r) * INV_T, &p2si[r], &p2ci[r]);
    const float b2v = __ldg(&b2[0]);

    __syncthreads();                             // sAB ready

    float y0[4] = {0.f, 0.f, 0.f, 0.f};
    float y1[4] = {0.f, 0.f, 0.f, 0.f};

#pragma unroll
    for (int c = 0; c < 4; ++c) {
        const int pr = 4 * lane + c;
        float4 v0 = g_SC4[pr][k0];               // rows i0, i0+1  (S,C,S,C)
        float4 v1 = g_SC4[pr][k0 + 1];           // rows i0+2, i0+3
        float4 ab = sAB[pr];
        const float Sv[4] = {v0.x, v0.z, v1.x, v1.z};
        const float Cv[4] = {v0.y, v0.w, v1.y, v1.w};
#pragma unroll
        for (int r = 0; r < 4; ++r) {
            float u = fmaf(p2ci[r], Sv[r], -p2si[r] * Cv[r]);
            float v = fmaf(p2si[r], Sv[r],  p2ci[r] * Cv[r]);
            y0[r] = fmaf(ab.x, u, fmaf(ab.y, v, y0[r]));
            y1[r] = fmaf(ab.z, u, fmaf(ab.w, v, y1[r]));
        }
    }
    if (lane == 0) {                             // b2 * prefix(sum_c x)
#pragma unroll
        for (int r = 0; r < 4; ++r) {
            float e = b2v * g_X[i0 + r];
            y0[r] += e; y1[r] += e;
        }
    }

    // Butterfly over lanes (h); 8 chains pipeline the shuffle latency.
#pragma unroll
    for (int off = 16; off > 0; off >>= 1) {
#pragma unroll
        for (int r = 0; r < 4; ++r) {
            y0[r] += __shfl_xor_sync(0xffffffffu, y0[r], off);
            y1[r] += __shfl_xor_sync(0xffffffffu, y1[r], off);
        }
    }
    if (lane == 0) {
#pragma unroll
        for (int r = 0; r < 4; ++r)
            ((float2*)y)[i0 + r] = make_float2(y0[r], y1[r]);
    }
}

// ---------------------------------------------------------------------------
// Inputs (metadata order): x[T*4], t[T], w1[H*3], b1[H], w2[H], b2[1],
// out_channels (unused; t = arange/T is exact fp32, computed inline).
// ---------------------------------------------------------------------------
extern "C" void kernel_launch(void* const* d_in, const int* in_sizes, int n_in,
                              void* d_out, int out_size)
{
    const float* x  = (const float*)d_in[0];
    const float* w1 = (const float*)d_in[2];
    const float* b1 = (const float*)d_in[3];
    const float* w2 = (const float*)d_in[4];
    const float* b2 = (const float*)d_in[5];
    float* y = (float*)d_out;

    ck_scan_kernel<<<NPAIR + 1, 256>>>(x, w1);
    ck_combine_kernel<<<32, 256>>>(w1, b1, w2, b2, y);
}